// round 7
// baseline (speedup 1.0000x reference)
#include <cuda_runtime.h>
#include <cstdint>

#define NSTEPS   730
#define NGRID    8000
#define HALF     4000        // thread owns cells gA and gA+HALF
#define UHL      15
#define CH       10          // timesteps per smem chunk; 730 = 73 * 10
#define BT       32          // one warp per block; 125 * 32 = 4000 pairs exact
#define NCHUNK   (NSTEPS / CH)
#define NEARZERO 1e-5f

typedef unsigned long long u64;

__device__ __forceinline__ float sigmoidf_(float x) {
    return 1.0f / (1.0f + __expf(-x));
}

// ---- packed f32x2 (Blackwell FFMA2 path, PTX-only) ----
__device__ __forceinline__ u64 pack2(float lo, float hi) {
    u64 r; asm("mov.b64 %0,{%1,%2};" : "=l"(r) : "f"(lo), "f"(hi)); return r;
}
__device__ __forceinline__ void unpack2(u64 v, float& lo, float& hi) {
    asm("mov.b64 {%0,%1},%2;" : "=f"(lo), "=f"(hi) : "l"(v));
}
__device__ __forceinline__ u64 fma2(u64 a, u64 b, u64 c) {
    u64 d; asm("fma.rn.f32x2 %0,%1,%2,%3;" : "=l"(d) : "l"(a), "l"(b), "l"(c)); return d;
}
__device__ __forceinline__ u64 mul2(u64 a, u64 b) {
    u64 d; asm("mul.rn.f32x2 %0,%1,%2;" : "=l"(d) : "l"(a), "l"(b)); return d;
}
__device__ __forceinline__ u64 add2(u64 a, u64 b) {
    u64 d; asm("add.rn.f32x2 %0,%1,%2;" : "=l"(d) : "l"(a), "l"(b)); return d;
}

__device__ __forceinline__ uint32_t smem_u32(const void* p) {
    uint32_t a;
    asm("{ .reg .u64 t; cvta.to.shared.u64 t, %1; cvt.u32.u64 %0, t; }" : "=r"(a) : "l"(p));
    return a;
}
__device__ __forceinline__ void cp_async16(uint32_t dst, const void* src) {
    asm volatile("cp.async.ca.shared.global [%0], [%1], 16;\n" :: "r"(dst), "l"(src));
}
__device__ __forceinline__ void cp_commit() { asm volatile("cp.async.commit_group;\n"); }
__device__ __forceinline__ void cp_wait1() { asm volatile("cp.async.wait_group 1;\n"); }

// smem staging: [2 buffers][2 cell-groups][CH steps][BT*3 floats]
__shared__ float sbuf[2][2][CH][BT * 3];

__device__ __forceinline__ void issue_chunk(const float* __restrict__ xphy,
                                            int c, int pb, int g0, int tid,
                                            uint32_t sbase) {
    const int t0 = c * CH;
    constexpr int ROW16 = BT * 3 / 4;          // 24 16B units per (group,row)
    constexpr int TOT16 = 2 * CH * ROW16;      // 480
    #pragma unroll 1
    for (int idx = tid; idx < TOT16; idx += BT) {
        int grp = idx / (CH * ROW16);
        int rem = idx - grp * (CH * ROW16);
        int row = rem / ROW16;
        int col = rem - row * ROW16;
        const float* src = xphy
            + ((size_t)(t0 + row) * NGRID + (size_t)(g0 + grp * HALF)) * 3 + col * 4;
        uint32_t dst = sbase
            + (uint32_t)((((pb * 2 + grp) * CH + row) * (BT * 3) + col * 4) * 4);
        cp_async16(dst, src);
    }
    cp_commit();
}

__global__ __launch_bounds__(BT, 1)
void hbv_kernel(const float* __restrict__ xphy,    // [T, G, 3]
                const float* __restrict__ params,  // [T, G, 16]
                float*       __restrict__ out)     // [T, G, 4]
{
    const int tid = threadIdx.x;
    const int g0  = blockIdx.x * BT;
    const uint32_t sbase = smem_u32(&sbuf[0][0][0][0]);

    int gi[2];
    gi[0] = g0 + tid;
    gi[1] = g0 + tid + HALF;

    // ---------------- per-cell parameters ----------------
    float pBETA[2], pFC[2], invfc[2], pK0[2], pK1[2], pK2[2], invlpfc[2];
    float pPERC[2], pUZL[2], pTT[2], pCFMAX[2], cfrcf[2], pCWH[2], pBETAET[2], pC[2];
    float wsc[2][UHL];

    #pragma unroll
    for (int c = 0; c < 2; c++) {
        const float* pr = params + ((size_t)(NSTEPS - 1) * NGRID + (size_t)gi[c]) * 16;
        float4 r0 = *(const float4*)(pr + 0);
        float4 r1 = *(const float4*)(pr + 4);
        float4 r2 = *(const float4*)(pr + 8);
        float4 r3 = *(const float4*)(pr + 12);

        pBETA[c]   = 1.0f   + sigmoidf_(r0.x) * 5.0f;
        pFC[c]     = 50.0f  + sigmoidf_(r0.y) * 950.0f;
        pK0[c]     = 0.05f  + sigmoidf_(r0.z) * 0.85f;
        pK1[c]     = 0.01f  + sigmoidf_(r0.w) * 0.49f;
        pK2[c]     = 0.001f + sigmoidf_(r1.x) * 0.199f;
        float pLP  = 0.2f   + sigmoidf_(r1.y) * 0.8f;
        pPERC[c]   =          sigmoidf_(r1.z) * 10.0f;
        pUZL[c]    =          sigmoidf_(r1.w) * 100.0f;
        pTT[c]     = -2.5f  + sigmoidf_(r2.x) * 5.0f;
        pCFMAX[c]  = 0.5f   + sigmoidf_(r2.y) * 9.5f;
        cfrcf[c]   =          sigmoidf_(r2.z) * 0.1f * pCFMAX[c];
        pCWH[c]    =          sigmoidf_(r2.w) * 0.2f;
        pBETAET[c] = 0.3f   + sigmoidf_(r3.x) * 4.7f;
        pC[c]      =          sigmoidf_(r3.y);
        float route_a =       sigmoidf_(r3.z) * 2.9f;
        float route_b =       sigmoidf_(r3.w) * 6.5f;

        invfc[c]   = __fdividef(1.0f, pFC[c]);
        invlpfc[c] = __fdividef(1.0f, pLP * pFC[c]);

        // gamma UH weights; Gamma(a)*theta^a cancels in normalization
        const float aa    = fmaxf(route_a, 0.0f) + 0.1f;
        const float theta = fmaxf(route_b, 0.0f) + 0.5f;
        const float am1   = aa - 1.0f;
        const float invth = __fdividef(1.0f, theta);
        float wsum = 0.0f;
        #pragma unroll
        for (int k = 0; k < UHL; k++) {
            float tk = (float)k + 0.5f;
            float v  = __expf(am1 * __logf(tk) - tk * invth);
            wsc[c][k] = v;
            wsum += v;
        }
        const float inv_wsum = __fdividef(1.0f, wsum);
        #pragma unroll
        for (int k = 0; k < UHL; k++) wsc[c][k] *= inv_wsum;
    }

    // packed weights: (cellA, cellB) per tap
    u64 wp[UHL];
    #pragma unroll
    for (int k = 0; k < UHL; k++) wp[k] = pack2(wsc[0][k], wsc[1][k]);

    // ---------------- state ----------------
    float SNOWPACK[2], MELTWATER[2], SM[2], SUZ[2], SLZ[2];
    #pragma unroll
    for (int c = 0; c < 2; c++) {
        SNOWPACK[c] = 0.001f; MELTWATER[c] = 0.001f;
        SM[c] = 0.001f; SUZ[c] = 0.001f; SLZ[c] = 0.001f;
    }
    // packed conv accumulators: per series, 14 future slots, lanes = (cellA, cellB)
    u64 A0[UHL - 1], A1[UHL - 1], A2[UHL - 1];
    #pragma unroll
    for (int j = 0; j < UHL - 1; j++) { A0[j] = 0ULL; A1[j] = 0ULL; A2[j] = 0ULL; }

    // prologue: issue chunks 0 and 1
    issue_chunk(xphy, 0, 0, g0, tid, sbase);
    issue_chunk(xphy, 1, 1, g0, tid, sbase);

    float4* __restrict__ out4 = (float4*)out;
    const int s3 = tid * 3;

    for (int k = 0; k < NCHUNK; k++) {
        const int pb = k & 1;
        cp_wait1();
        __syncthreads();

        #pragma unroll
        for (int u = 0; u < CH; u++) {
            const int t = k * CH + u;
            float Q0v[2], Q1v[2], Q2v[2];

            #pragma unroll
            for (int c = 0; c < 2; c++) {
                const float P   = sbuf[pb][c][u][s3 + 0];
                const float Tt  = sbuf[pb][c][u][s3 + 1];
                const float PET = sbuf[pb][c][u][s3 + 2];

                // ---- SM critical chain head ----
                const float sw = fminf(__expf(pBETA[c] * __logf(SM[c] * invfc[c])), 1.0f);

                // ---- snow (parallel branch) ----
                const float RAIN = (Tt >= pTT[c]) ? P : 0.0f;
                const float SNOW = (Tt <  pTT[c]) ? P : 0.0f;
                float sp = SNOWPACK[c] + SNOW;
                const float melt = fminf(fmaxf(pCFMAX[c] * (Tt - pTT[c]), 0.0f), sp);
                float mw = MELTWATER[c] + melt;
                sp -= melt;
                const float refreeze = fminf(fmaxf(cfrcf[c] * (pTT[c] - Tt), 0.0f), mw);
                sp += refreeze;
                mw -= refreeze;
                const float tosoil = fmaxf(mw - pCWH[c] * sp, 0.0f);
                MELTWATER[c] = mw - tosoil;
                SNOWPACK[c]  = sp;

                // ---- soil moisture ----
                const float rt   = RAIN + tosoil;
                const float smrt = SM[c] + rt;
                const float recharge = rt * sw;
                const float SM1 = fmaf(-rt, sw, smrt);
                const float excess = fmaxf(SM1 - pFC[c], 0.0f);
                const float SM2 = fminf(SM1, pFC[c]);
                // capillary (min-with-SLZ redundant: C<=1 and SM2<=FC)
                const float cSLZ = pC[c] * SLZ[c];
                const float cap  = cSLZ * fmaf(-invfc[c], SM2, 1.0f);
                const float SM3  = fmaxf(SM2 + cap, NEARZERO);
                const float SLZa = fmaxf(SLZ[c] - cap, NEARZERO);

                // ---- evapotranspiration ----
                const float evr = fminf(SM3 * invlpfc[c], 1.0f);
                const float ef  = __expf(pBETAET[c] * __logf(evr));
                const float ET  = fminf(PET * ef, SM3);
                SM[c] = fmaxf(SM3 - ET, NEARZERO);

                // ---- response routine ----
                float suz = SUZ[c] + recharge + excess;
                const float perc = fminf(suz, pPERC[c]);
                suz -= perc;
                const float Q0 = pK0[c] * fmaxf(suz - pUZL[c], 0.0f);
                suz -= Q0;
                const float Q1 = pK1[c] * suz;
                SUZ[c] = suz - Q1;
                float slz = SLZa + perc;
                const float Q2 = pK2[c] * slz;
                SLZ[c] = slz - Q2;

                Q0v[c] = Q0; Q1v[c] = Q1; Q2v[c] = Q2;
            }

            // ---- packed 15-tap conv: lanes = (cellA, cellB), both cells at once ----
            const u64 q0 = pack2(Q0v[0], Q0v[1]);
            const u64 q1 = pack2(Q1v[0], Q1v[1]);
            const u64 q2 = pack2(Q2v[0], Q2v[1]);

            const u64 y0 = fma2(wp[0], q0, A0[0]);
            const u64 y1 = fma2(wp[0], q1, A1[0]);
            const u64 y2 = fma2(wp[0], q2, A2[0]);
            #pragma unroll
            for (int j = 0; j < UHL - 2; j++) {
                A0[j] = fma2(wp[j + 1], q0, A0[j + 1]);
                A1[j] = fma2(wp[j + 1], q1, A1[j + 1]);
                A2[j] = fma2(wp[j + 1], q2, A2[j + 1]);
            }
            A0[UHL - 2] = mul2(wp[UHL - 1], q0);
            A1[UHL - 2] = mul2(wp[UHL - 1], q1);
            A2[UHL - 2] = mul2(wp[UHL - 1], q2);

            const u64 ysum = add2(add2(y0, y1), y2);

            float s_lo, s_hi, y0lo, y0hi, y1lo, y1hi, y2lo, y2hi;
            unpack2(ysum, s_lo, s_hi);
            unpack2(y0, y0lo, y0hi);
            unpack2(y1, y1lo, y1hi);
            unpack2(y2, y2lo, y2hi);

            float4 oA; oA.x = s_lo; oA.y = y0lo; oA.z = y1lo; oA.w = y2lo;
            float4 oB; oB.x = s_hi; oB.y = y0hi; oB.z = y1hi; oB.w = y2hi;
            out4[(size_t)t * NGRID + (size_t)gi[0]] = oA;
            out4[(size_t)t * NGRID + (size_t)gi[1]] = oB;
        }

        __syncthreads();
        if (k + 2 < NCHUNK)
            issue_chunk(xphy, k + 2, pb, g0, tid, sbase);
        else
            cp_commit();
    }
}

extern "C" void kernel_launch(void* const* d_in, const int* in_sizes, int n_in,
                              void* d_out, int out_size) {
    const float* xphy   = (const float*)d_in[0];   // [730, 8000, 3]
    const float* params = (const float*)d_in[1];   // [730, 8000, 16]
    float* out = (float*)d_out;                    // [730, 8000, 4]
    (void)in_sizes; (void)n_in; (void)out_size;

    dim3 block(BT);
    dim3 grid(HALF / BT);   // 125 blocks, 1 warp each, 2 cells per thread
    hbv_kernel<<<grid, block>>>(xphy, params, out);
}

// round 8
// speedup vs baseline: 1.7335x; 1.7335x over previous
#include <cuda_runtime.h>
#include <cstdint>

#define NSTEPS   730
#define NGRID    8000
#define UHL      15
#define CH       10          // timesteps per smem chunk; 730 = 73 * 10
#define BT       32          // one warp per block, warp-private staging
#define NCHUNK   (NSTEPS / CH)
#define PIPE     4           // cp.async pipeline depth
#define NEARZERO 1e-5f

__device__ __forceinline__ float sigmoidf_(float x) {
    return 1.0f / (1.0f + __expf(-x));
}

__device__ __forceinline__ uint32_t smem_u32(const void* p) {
    uint32_t a;
    asm("{ .reg .u64 t; cvta.to.shared.u64 t, %1; cvt.u32.u64 %0, t; }" : "=r"(a) : "l"(p));
    return a;
}
__device__ __forceinline__ void cp_async16(uint32_t dst, const void* src) {
    asm volatile("cp.async.ca.shared.global [%0], [%1], 16;\n" :: "r"(dst), "l"(src));
}
__device__ __forceinline__ void cp_commit() { asm volatile("cp.async.commit_group;\n"); }
__device__ __forceinline__ void cp_wait3() { asm volatile("cp.async.wait_group 3;\n"); }

// smem staging: [PIPE buffers][CH steps][BT*3 floats]   (one warp per block)
__shared__ float sbuf[PIPE][CH][BT * 3];

__device__ __forceinline__ void issue_chunk(const float* __restrict__ xphy,
                                            int c, int pb, int g0, int tid,
                                            uint32_t sbase) {
    const int t0 = c * CH;
    constexpr int ROW16 = BT * 3 / 4;        // 24 16B units per row
    constexpr int TOT16 = CH * ROW16;        // 240
    #pragma unroll 1
    for (int idx = tid; idx < TOT16; idx += BT) {
        int row = idx / ROW16;
        int col = idx - row * ROW16;
        const float* src = xphy + ((size_t)(t0 + row) * NGRID + (size_t)g0) * 3 + col * 4;
        uint32_t dst = sbase + (uint32_t)(((pb * CH + row) * (BT * 3) + col * 4) * 4);
        cp_async16(dst, src);
    }
    cp_commit();
}

__global__ __launch_bounds__(BT, 1)
void hbv_kernel(const float* __restrict__ xphy,    // [T, G, 3]
                const float* __restrict__ params,  // [T, G, 16]
                float*       __restrict__ out)     // [T, G, 4]
{
    const int tid = threadIdx.x;
    const int g0  = blockIdx.x * BT;
    const int g   = g0 + tid;
    const uint32_t sbase = smem_u32(&sbuf[0][0][0]);

    // ---------------- static parameters (last timestep only) ----------------
    const float* pr = params + ((size_t)(NSTEPS - 1) * NGRID + (size_t)g) * 16;
    float4 r0 = *(const float4*)(pr + 0);
    float4 r1 = *(const float4*)(pr + 4);
    float4 r2 = *(const float4*)(pr + 8);
    float4 r3 = *(const float4*)(pr + 12);

    const float parBETA   = 1.0f   + sigmoidf_(r0.x) * 5.0f;
    const float parFC     = 50.0f  + sigmoidf_(r0.y) * 950.0f;
    const float parK0     = 0.05f  + sigmoidf_(r0.z) * 0.85f;
    const float parK1     = 0.01f  + sigmoidf_(r0.w) * 0.49f;
    const float parK2     = 0.001f + sigmoidf_(r1.x) * 0.199f;
    const float parLP     = 0.2f   + sigmoidf_(r1.y) * 0.8f;
    const float parPERC   =          sigmoidf_(r1.z) * 10.0f;
    const float parUZL    =          sigmoidf_(r1.w) * 100.0f;
    const float parTT     = -2.5f  + sigmoidf_(r2.x) * 5.0f;
    const float parCFMAX  = 0.5f   + sigmoidf_(r2.y) * 9.5f;
    const float cfr_cfmax =          sigmoidf_(r2.z) * 0.1f * parCFMAX;
    const float parCWH    =          sigmoidf_(r2.w) * 0.2f;
    const float parBETAET = 0.3f   + sigmoidf_(r3.x) * 4.7f;
    const float parC      =          sigmoidf_(r3.y);
    const float route_a   =          sigmoidf_(r3.z) * 2.9f;
    const float route_b   =          sigmoidf_(r3.w) * 6.5f;

    const float inv_fc   = __fdividef(1.0f, parFC);
    const float inv_lpfc = __fdividef(1.0f, parLP * parFC);

    // gamma UH weights; Gamma(a)*theta^a cancels in normalization
    const float aa    = fmaxf(route_a, 0.0f) + 0.1f;
    const float theta = fmaxf(route_b, 0.0f) + 0.5f;
    const float am1   = aa - 1.0f;
    const float invth = __fdividef(1.0f, theta);

    float w[UHL];
    float wsum = 0.0f;
    #pragma unroll
    for (int k = 0; k < UHL; k++) {
        float tk = (float)k + 0.5f;
        float v  = __expf(am1 * __logf(tk) - tk * invth);
        w[k] = v;
        wsum += v;
    }
    const float inv_wsum = __fdividef(1.0f, wsum);
    #pragma unroll
    for (int k = 0; k < UHL; k++) w[k] *= inv_wsum;

    // ---------------- state ----------------
    float SNOWPACK = 0.001f, MELTWATER = 0.001f, SM = 0.001f, SUZ = 0.001f, SLZ = 0.001f;
    float a0[UHL - 1], a1[UHL - 1], a2[UHL - 1];
    #pragma unroll
    for (int j = 0; j < UHL - 1; j++) { a0[j] = 0.0f; a1[j] = 0.0f; a2[j] = 0.0f; }

    // prologue: fill 4-deep pipeline
    issue_chunk(xphy, 0, 0, g0, tid, sbase);
    issue_chunk(xphy, 1, 1, g0, tid, sbase);
    issue_chunk(xphy, 2, 2, g0, tid, sbase);
    issue_chunk(xphy, 3, 3, g0, tid, sbase);

    float4* __restrict__ outp = (float4*)out + g;   // advance by NGRID per step
    const int s3 = tid * 3;

    for (int k = 0; k < NCHUNK; k++) {
        const int pb = k & (PIPE - 1);
        cp_wait3();            // chunk k complete (<=3 newer groups in flight)
        __syncwarp();          // publish other lanes' copies within the warp

        // hoist the whole chunk's inputs into registers (batched LDS, MLP)
        float Pv[CH], Tv[CH], Ev[CH];
        #pragma unroll
        for (int u = 0; u < CH; u++) {
            Pv[u] = sbuf[pb][u][s3 + 0];
            Tv[u] = sbuf[pb][u][s3 + 1];
            Ev[u] = sbuf[pb][u][s3 + 2];
        }
        __syncwarp();          // all lanes done reading slot pb

        // refill slot pb with chunk k+PIPE (or empty group to keep accounting)
        if (k + PIPE < NCHUNK)
            issue_chunk(xphy, k + PIPE, pb, g0, tid, sbase);
        else
            cp_commit();

        #pragma unroll
        for (int u = 0; u < CH; u++) {
            const float P   = Pv[u];
            const float Tt  = Tv[u];
            const float PET = Ev[u];

            // ---- SM critical chain head ----
            const float sw = fminf(__expf(parBETA * __logf(SM * inv_fc)), 1.0f);

            // ---- snow (parallel branch) ----
            const float RAIN = (Tt >= parTT) ? P : 0.0f;
            const float SNOW = (Tt <  parTT) ? P : 0.0f;
            float sp = SNOWPACK + SNOW;
            const float melt = fminf(fmaxf(parCFMAX * (Tt - parTT), 0.0f), sp);
            float mw = MELTWATER + melt;
            sp -= melt;
            const float refreeze = fminf(fmaxf(cfr_cfmax * (parTT - Tt), 0.0f), mw);
            sp += refreeze;
            mw -= refreeze;
            const float tosoil = fmaxf(mw - parCWH * sp, 0.0f);
            MELTWATER = mw - tosoil;
            SNOWPACK  = sp;

            // ---- soil moisture ----
            const float rt   = RAIN + tosoil;
            const float smrt = SM + rt;
            const float recharge = rt * sw;
            const float SM1 = fmaf(-rt, sw, smrt);
            const float excess = fmaxf(SM1 - parFC, 0.0f);
            const float SM2 = fminf(SM1, parFC);
            // capillary (min-with-SLZ redundant: C<=1 and SM2<=FC)
            const float cSLZ = parC * SLZ;
            const float cap  = cSLZ * fmaf(-inv_fc, SM2, 1.0f);
            const float SM3  = fmaxf(SM2 + cap, NEARZERO);
            const float SLZa = fmaxf(SLZ - cap, NEARZERO);

            // ---- evapotranspiration ----
            const float evr = fminf(SM3 * inv_lpfc, 1.0f);
            const float ef  = __expf(parBETAET * __logf(evr));
            const float ET  = fminf(PET * ef, SM3);
            SM = fmaxf(SM3 - ET, NEARZERO);

            // ---- response routine ----
            float suz = SUZ + recharge + excess;
            const float perc = fminf(suz, parPERC);
            suz -= perc;
            const float Q0 = parK0 * fmaxf(suz - parUZL, 0.0f);
            suz -= Q0;
            const float Q1 = parK1 * suz;
            SUZ = suz - Q1;
            float slz = SLZa + perc;
            const float Q2 = parK2 * slz;
            SLZ = slz - Q2;

            // ---- 15-tap causal conv via shift-FMA accumulators ----
            const float y0 = a0[0] + w[0] * Q0;
            const float y1 = a1[0] + w[0] * Q1;
            const float y2 = a2[0] + w[0] * Q2;
            #pragma unroll
            for (int j = 0; j < UHL - 2; j++) {
                a0[j] = a0[j + 1] + w[j + 1] * Q0;
                a1[j] = a1[j + 1] + w[j + 1] * Q1;
                a2[j] = a2[j + 1] + w[j + 1] * Q2;
            }
            a0[UHL - 2] = w[UHL - 1] * Q0;
            a1[UHL - 2] = w[UHL - 1] * Q1;
            a2[UHL - 2] = w[UHL - 1] * Q2;

            float4 o;
            o.x = y0 + y1 + y2;
            o.y = y0;
            o.z = y1;
            o.w = y2;
            *outp = o;
            outp += NGRID;
        }
    }
}

extern "C" void kernel_launch(void* const* d_in, const int* in_sizes, int n_in,
                              void* d_out, int out_size) {
    const float* xphy   = (const float*)d_in[0];   // [730, 8000, 3]
    const float* params = (const float*)d_in[1];   // [730, 8000, 16]
    float* out = (float*)d_out;                    // [730, 8000, 4]
    (void)in_sizes; (void)n_in; (void)out_size;

    dim3 block(BT);
    dim3 grid(NGRID / BT);   // 250 warp-private blocks
    hbv_kernel<<<grid, block>>>(xphy, params, out);
}

// round 11
// speedup vs baseline: 2.4370x; 1.4058x over previous
#include <cuda_runtime.h>
#include <cstdint>

#define NSTEPS   730
#define NGRID    8000
#define UHL      15
#define CH       10          // timesteps per smem chunk; 730 = 73 * 10
#define BT       32          // one warp per block, warp-private staging
#define NCHUNK   (NSTEPS / CH)
#define PIPE     4           // cp.async pipeline depth
#define NEARZERO 1e-5f

__device__ __forceinline__ float ex2_(float x) {
    float r; asm("ex2.approx.ftz.f32 %0, %1;" : "=f"(r) : "f"(x)); return r;
}
__device__ __forceinline__ float lg2_(float x) {
    float r; asm("lg2.approx.ftz.f32 %0, %1;" : "=f"(r) : "f"(x)); return r;
}

__device__ __forceinline__ float sigmoidf_(float x) {
    return 1.0f / (1.0f + __expf(-x));
}

__device__ __forceinline__ uint32_t smem_u32(const void* p) {
    uint32_t a;
    asm("{ .reg .u64 t; cvta.to.shared.u64 t, %1; cvt.u32.u64 %0, t; }" : "=r"(a) : "l"(p));
    return a;
}
__device__ __forceinline__ void cp_async16(uint32_t dst, const void* src) {
    asm volatile("cp.async.ca.shared.global [%0], [%1], 16;\n" :: "r"(dst), "l"(src));
}
__device__ __forceinline__ void cp_commit() { asm volatile("cp.async.commit_group;\n"); }
__device__ __forceinline__ void cp_wait3() { asm volatile("cp.async.wait_group 3;\n"); }

// smem staging: [PIPE buffers][CH steps][BT*3 floats]   (one warp per block)
__shared__ float sbuf[PIPE][CH][BT * 3];

__device__ __forceinline__ void issue_chunk(const float* __restrict__ xphy,
                                            int c, int pb, int g0, int tid,
                                            uint32_t sbase) {
    const int t0 = c * CH;
    constexpr int ROW16 = BT * 3 / 4;        // 24 16B units per row
    constexpr int TOT16 = CH * ROW16;        // 240
    #pragma unroll 1
    for (int idx = tid; idx < TOT16; idx += BT) {
        int row = idx / ROW16;
        int col = idx - row * ROW16;
        const float* src = xphy + ((size_t)(t0 + row) * NGRID + (size_t)g0) * 3 + col * 4;
        uint32_t dst = sbase + (uint32_t)(((pb * CH + row) * (BT * 3) + col * 4) * 4);
        cp_async16(dst, src);
    }
    cp_commit();
}

__global__ __launch_bounds__(BT, 1)
void hbv_kernel(const float* __restrict__ xphy,    // [T, G, 3]
                const float* __restrict__ params,  // [T, G, 16]
                float*       __restrict__ out)     // [T, G, 4]
{
    const int tid = threadIdx.x;
    const int g0  = blockIdx.x * BT;
    const int g   = g0 + tid;
    const uint32_t sbase = smem_u32(&sbuf[0][0][0]);

    // ---------------- static parameters (last timestep only) ----------------
    const float* pr = params + ((size_t)(NSTEPS - 1) * NGRID + (size_t)g) * 16;
    float4 r0 = *(const float4*)(pr + 0);
    float4 r1 = *(const float4*)(pr + 4);
    float4 r2 = *(const float4*)(pr + 8);
    float4 r3 = *(const float4*)(pr + 12);

    const float parBETA   = 1.0f   + sigmoidf_(r0.x) * 5.0f;
    const float parFC     = 50.0f  + sigmoidf_(r0.y) * 950.0f;
    const float parK0     = 0.05f  + sigmoidf_(r0.z) * 0.85f;
    const float parK1     = 0.01f  + sigmoidf_(r0.w) * 0.49f;
    const float parK2     = 0.001f + sigmoidf_(r1.x) * 0.199f;
    const float parLP     = 0.2f   + sigmoidf_(r1.y) * 0.8f;
    const float parPERC   =          sigmoidf_(r1.z) * 10.0f;
    const float parUZL    =          sigmoidf_(r1.w) * 100.0f;
    const float parTT     = -2.5f  + sigmoidf_(r2.x) * 5.0f;
    const float parCFMAX  = 0.5f   + sigmoidf_(r2.y) * 9.5f;
    const float cfr_cfmax =          sigmoidf_(r2.z) * 0.1f * parCFMAX;
    const float parCWH    =          sigmoidf_(r2.w) * 0.2f;
    const float parBETAET = 0.3f   + sigmoidf_(r3.x) * 4.7f;
    const float parC      =          sigmoidf_(r3.y);
    const float route_a   =          sigmoidf_(r3.z) * 2.9f;
    const float route_b   =          sigmoidf_(r3.w) * 6.5f;

    const float inv_fc   = __fdividef(1.0f, parFC);
    // pow folding: (x/s)^b = ex2(b*lg2(x) - b*lg2(s))
    const float nBlg2FC  = -parBETA   * lg2_(parFC);
    const float nBElg2LP = -parBETAET * lg2_(parLP * parFC);

    // gamma UH weights; Gamma(a)*theta^a cancels in normalization
    const float aa    = fmaxf(route_a, 0.0f) + 0.1f;
    const float theta = fmaxf(route_b, 0.0f) + 0.5f;
    const float am1   = aa - 1.0f;
    const float invth = __fdividef(1.0f, theta);

    float w[UHL];
    float wsum = 0.0f;
    #pragma unroll
    for (int k = 0; k < UHL; k++) {
        float tk = (float)k + 0.5f;
        float v  = __expf(am1 * __logf(tk) - tk * invth);
        w[k] = v;
        wsum += v;
    }
    const float inv_wsum = __fdividef(1.0f, wsum);
    #pragma unroll
    for (int k = 0; k < UHL; k++) w[k] *= inv_wsum;

    // ---------------- state ----------------
    float SNOWPACK = 0.001f, MELTWATER = 0.001f, SM = 0.001f, SUZ = 0.001f, SLZ = 0.001f;
    float a0[UHL - 1], a1[UHL - 1], a2[UHL - 1];
    #pragma unroll
    for (int j = 0; j < UHL - 1; j++) { a0[j] = 0.0f; a1[j] = 0.0f; a2[j] = 0.0f; }

    // software-pipeline carries: sw for the upcoming step, Qs of previous step
    float sw = fminf(ex2_(fmaf(parBETA, lg2_(SM), nBlg2FC)), 1.0f);
    float pQ0 = 0.0f, pQ1 = 0.0f, pQ2 = 0.0f;   // fictitious step -1 (zeros: exact)

    // prologue: fill 4-deep pipeline
    issue_chunk(xphy, 0, 0, g0, tid, sbase);
    issue_chunk(xphy, 1, 1, g0, tid, sbase);
    issue_chunk(xphy, 2, 2, g0, tid, sbase);
    issue_chunk(xphy, 3, 3, g0, tid, sbase);

    float4* __restrict__ out4 = (float4*)out;
    const int s3 = tid * 3;

    for (int k = 0; k < NCHUNK; k++) {
        const int pb = k & (PIPE - 1);
        cp_wait3();            // chunk k complete (<=3 newer groups in flight)
        __syncwarp();          // publish other lanes' copies within the warp

        #pragma unroll
        for (int u = 0; u < CH; u++) {
            const int t = k * CH + u;
            const float P   = sbuf[pb][u][s3 + 0];
            const float Tt  = sbuf[pb][u][s3 + 1];
            const float PET = sbuf[pb][u][s3 + 2];

            // ---- snow chain ----
            const float RAIN = (Tt >= parTT) ? P : 0.0f;
            const float SNOW = (Tt <  parTT) ? P : 0.0f;
            float sp = SNOWPACK + SNOW;
            const float melt = fminf(fmaxf(parCFMAX * (Tt - parTT), 0.0f), sp);
            float mw = MELTWATER + melt;
            sp -= melt;
            const float refreeze = fminf(fmaxf(cfr_cfmax * (parTT - Tt), 0.0f), mw);
            sp += refreeze;
            mw -= refreeze;
            const float tosoil = fmaxf(mw - parCWH * sp, 0.0f);
            MELTWATER = mw - tosoil;
            SNOWPACK  = sp;

            // ---- soil moisture (sw precomputed last iteration) ----
            const float rt   = RAIN + tosoil;
            const float smrt = SM + rt;
            const float recharge = rt * sw;
            const float SM1 = fmaf(-rt, sw, smrt);
            const float excess = fmaxf(SM1 - parFC, 0.0f);
            const float SM2 = fminf(SM1, parFC);
            // capillary (min-with-SLZ redundant: C<=1 and SM2<=FC)
            const float cSLZ = parC * SLZ;
            const float cap  = cSLZ * fmaf(-inv_fc, SM2, 1.0f);
            const float SM3  = fmaxf(SM2 + cap, NEARZERO);
            const float SLZa = fmaxf(SLZ - cap, NEARZERO);

            // ---- launch evapfactor pow: min((SM3/(LP*FC))^BETAET, 1) ----
            const float ef_raw = ex2_(fmaf(parBETAET, lg2_(SM3), nBElg2LP));

            // ==== FILL the pow latency: conv + store of PREVIOUS step ====
            {
                const float y0 = a0[0] + w[0] * pQ0;
                const float y1 = a1[0] + w[0] * pQ1;
                const float y2 = a2[0] + w[0] * pQ2;
                #pragma unroll
                for (int j = 0; j < UHL - 2; j++) {
                    a0[j] = a0[j + 1] + w[j + 1] * pQ0;
                    a1[j] = a1[j + 1] + w[j + 1] * pQ1;
                    a2[j] = a2[j + 1] + w[j + 1] * pQ2;
                }
                a0[UHL - 2] = w[UHL - 1] * pQ0;
                a1[UHL - 2] = w[UHL - 1] * pQ1;
                a2[UHL - 2] = w[UHL - 1] * pQ2;
                if (t > 0) {
                    float4 o;
                    o.x = y0 + y1 + y2;
                    o.y = y0;
                    o.z = y1;
                    o.w = y2;
                    out4[(size_t)(t - 1) * NGRID + g] = o;
                }
            }

            // ---- ET and SM update ----
            const float ef = fminf(ef_raw, 1.0f);
            const float ET = fminf(PET * ef, SM3);
            SM = fmaxf(SM3 - ET, NEARZERO);

            // ---- launch next step's soil-wetness pow: min((SM/FC)^BETA, 1) ----
            sw = fminf(ex2_(fmaf(parBETA, lg2_(SM), nBlg2FC)), 1.0f);

            // ==== FILL: response routine (independent of sw) ====
            float suz = SUZ + recharge + excess;
            const float perc = fminf(suz, parPERC);
            suz -= perc;
            const float Q0 = parK0 * fmaxf(suz - parUZL, 0.0f);
            suz -= Q0;
            const float Q1 = parK1 * suz;
            SUZ = suz - Q1;
            float slz = SLZa + perc;
            const float Q2 = parK2 * slz;
            SLZ = slz - Q2;

            pQ0 = Q0; pQ1 = Q1; pQ2 = Q2;
        }

        __syncwarp();          // all lanes done reading slot pb
        if (k + PIPE < NCHUNK)
            issue_chunk(xphy, k + PIPE, pb, g0, tid, sbase);
        else
            cp_commit();
    }

    // epilogue: conv + store of the final step
    {
        const float y0 = a0[0] + w[0] * pQ0;
        const float y1 = a1[0] + w[0] * pQ1;
        const float y2 = a2[0] + w[0] * pQ2;
        float4 o;
        o.x = y0 + y1 + y2;
        o.y = y0;
        o.z = y1;
        o.w = y2;
        out4[(size_t)(NSTEPS - 1) * NGRID + g] = o;
    }
}

extern "C" void kernel_launch(void* const* d_in, const int* in_sizes, int n_in,
                              void* d_out, int out_size) {
    const float* xphy   = (const float*)d_in[0];   // [730, 8000, 3]
    const float* params = (const float*)d_in[1];   // [730, 8000, 16]
    float* out = (float*)d_out;                    // [730, 8000, 4]
    (void)in_sizes; (void)n_in; (void)out_size;

    dim3 block(BT);
    dim3 grid(NGRID / BT);   // 250 warp-private blocks
    hbv_kernel<<<grid, block>>>(xphy, params, out);
}